// round 5
// baseline (speedup 1.0000x reference)
#include <cuda_runtime.h>
#include <cuda_bf16.h>
#include <cstdint>

// ---------------------------------------------------------------------------
// Problem constants (from reference_code)
// ---------------------------------------------------------------------------
#define N_NODES 50000
#define N_EDGES 800000
#define IN_CH   128
#define MID_CH  256

// ---------------------------------------------------------------------------
// Scratch (device globals; no dynamic allocation allowed).
// __align__(16) so float4 accesses are always legal.
// ---------------------------------------------------------------------------
__device__ __align__(16) float g_deg[N_NODES];
__device__ __align__(16) float g_dis[N_NODES];
__device__ __align__(16) float g_h  [(size_t)N_NODES * IN_CH];   // x @ W_conv, later residual output
__device__ __align__(16) float g_agg[(size_t)N_NODES * IN_CH];   // scatter-add accumulator
__device__ __align__(16) float g_h1 [(size_t)N_NODES * MID_CH];
__device__ __align__(16) float g_h2 [(size_t)N_NODES * MID_CH];

// ---------------------------------------------------------------------------
// K1: init degree to 1.0 (self loop)
// ---------------------------------------------------------------------------
__global__ void k_deg_init()
{
    int i = blockIdx.x * blockDim.x + threadIdx.x;
    if (i < N_NODES) g_deg[i] = 1.0f;
}

// ---------------------------------------------------------------------------
// K2: count incoming edges per dst  (edge indices are INT32)
// ---------------------------------------------------------------------------
__global__ void k_deg_count(const int* __restrict__ dst)
{
    int e = blockIdx.x * blockDim.x + threadIdx.x;
    if (e < N_EDGES) atomicAdd(&g_deg[dst[e]], 1.0f);
}

// ---------------------------------------------------------------------------
// K3: dis = rsqrt(deg)  (deg >= 1 always due to self loop)
// ---------------------------------------------------------------------------
__global__ void k_dis()
{
    int i = blockIdx.x * blockDim.x + threadIdx.x;
    if (i < N_NODES) g_dis[i] = rsqrtf(g_deg[i]);
}

// ---------------------------------------------------------------------------
// Tiled fp32 GEMM body: C[M,N] = A[M,K] @ B[K,N]  (+bias, +relu optional)
// BM=64, BN=64, BK=16, 256 threads (16x16), 4x4 microtile.
// N, K compile-time (multiples of 64 / 16); M guarded.
// ---------------------------------------------------------------------------
#define BM 64
#define BN 64
#define BK 16
#define TM 4
#define TN 4

template<int N, int K, bool RELU, bool BIAS>
__device__ __forceinline__
void gemm_body(const float* __restrict__ A, const float* __restrict__ B,
               const float* __restrict__ bias, float* __restrict__ C, int M)
{
    __shared__ float As[BK][BM];
    __shared__ float Bs[BK][BN];

    const int tid = threadIdx.x;
    const int tr  = tid >> 4;       // 0..15
    const int tc  = tid & 15;       // 0..15
    const int row0 = blockIdx.y * BM;
    const int col0 = blockIdx.x * BN;

    float acc[TM][TN];
#pragma unroll
    for (int i = 0; i < TM; i++)
#pragma unroll
        for (int j = 0; j < TN; j++) acc[i][j] = 0.0f;

#pragma unroll 1
    for (int k0 = 0; k0 < K; k0 += BK) {
        // A tile: BM x BK (1024 elems / 256 threads = 4 each), stored transposed
#pragma unroll
        for (int t = 0; t < 4; t++) {
            int idx = tid + t * 256;
            int r = idx >> 4;          // idx / BK
            int c = idx & 15;
            int gr = row0 + r;
            As[c][r] = (gr < M) ? A[(size_t)gr * K + k0 + c] : 0.0f;
        }
        // B tile: BK x BN (1024 elems)
#pragma unroll
        for (int t = 0; t < 4; t++) {
            int idx = tid + t * 256;
            int r = idx >> 6;          // idx / BN
            int c = idx & 63;
            Bs[r][c] = B[(size_t)(k0 + r) * N + col0 + c];
        }
        __syncthreads();

#pragma unroll
        for (int kk = 0; kk < BK; kk++) {
            float a[TM], b[TN];
#pragma unroll
            for (int i = 0; i < TM; i++) a[i] = As[kk][tr * TM + i];
#pragma unroll
            for (int j = 0; j < TN; j++) b[j] = Bs[kk][tc * TN + j];
#pragma unroll
            for (int i = 0; i < TM; i++)
#pragma unroll
                for (int j = 0; j < TN; j++) acc[i][j] = fmaf(a[i], b[j], acc[i][j]);
        }
        __syncthreads();
    }

#pragma unroll
    for (int i = 0; i < TM; i++) {
        int gr = row0 + tr * TM + i;
        if (gr >= M) continue;
#pragma unroll
        for (int j = 0; j < TN; j++) {
            int gc = col0 + tc * TN + j;
            float v = acc[i][j];
            if (BIAS) v += bias[gc];
            if (RELU) v = fmaxf(v, 0.0f);
            C[(size_t)gr * N + gc] = v;
        }
    }
}

// Thin wrappers: scratch buffers referenced directly (device-side symbols).
__global__ __launch_bounds__(256)
void k_gemm_conv(const float* __restrict__ x, const float* __restrict__ W)
{
    gemm_body<IN_CH, IN_CH, false, false>(x, W, nullptr, g_h, N_NODES);
}

__global__ __launch_bounds__(256)
void k_gemm_mlp1(const float* __restrict__ W1, const float* __restrict__ b1)
{
    gemm_body<MID_CH, IN_CH, true, true>(g_h, W1, b1, g_h1, N_NODES);
}

__global__ __launch_bounds__(256)
void k_gemm_mlp2(const float* __restrict__ W2, const float* __restrict__ b2)
{
    gemm_body<MID_CH, MID_CH, true, true>(g_h1, W2, b2, g_h2, N_NODES);
}

// ---------------------------------------------------------------------------
// K5: self-loop contribution: agg[i,:] = dis[i]^2 * h[i,:]
// (also serves as the g_agg initializer — must run before k_scatter)
// ---------------------------------------------------------------------------
__global__ void k_selfloop()
{
    size_t i = (size_t)blockIdx.x * blockDim.x + threadIdx.x;
    if (i >= (size_t)N_NODES * IN_CH) return;
    int node = (int)(i >> 7);     // IN_CH = 128
    float d = g_dis[node];
    g_agg[i] = d * d * g_h[i];
}

// ---------------------------------------------------------------------------
// K6: edge scatter: agg[dst,:] += dis[src]*dis[dst] * h[src,:]
// One warp per edge; each lane handles 4 contiguous channels (float4 load).
// ---------------------------------------------------------------------------
__global__ __launch_bounds__(256)
void k_scatter(const int* __restrict__ src, const int* __restrict__ dst)
{
    int e = blockIdx.x * 8 + (threadIdx.x >> 5);
    if (e >= N_EDGES) return;
    int lane = threadIdx.x & 31;

    int s = src[e];
    int d = dst[e];
    float nrm = g_dis[s] * g_dis[d];

    const float4* hrow = reinterpret_cast<const float4*>(g_h + (size_t)s * IN_CH);
    float4 v = hrow[lane];

    float* ag = g_agg + (size_t)d * IN_CH + lane * 4;
    atomicAdd(ag + 0, nrm * v.x);
    atomicAdd(ag + 1, nrm * v.y);
    atomicAdd(ag + 2, nrm * v.z);
    atomicAdd(ag + 3, nrm * v.w);
}

// ---------------------------------------------------------------------------
// K7: post-conv epilogue: h = relu(agg + b_conv) + x   (residual)
// ---------------------------------------------------------------------------
__global__ void k_postconv(const float* __restrict__ x, const float* __restrict__ b_conv)
{
    size_t i = (size_t)blockIdx.x * blockDim.x + threadIdx.x;
    if (i >= (size_t)N_NODES * IN_CH) return;
    int c = (int)(i & (IN_CH - 1));
    float v = g_agg[i] + b_conv[c];
    v = fmaxf(v, 0.0f);
    g_h[i] = v + x[i];
}

// ---------------------------------------------------------------------------
// K10: final layer: out[i] = dot(h2[i,:], W3) + b3   (W3: [256,1])
// One warp per node, 8 warps per block.
// ---------------------------------------------------------------------------
__global__ __launch_bounds__(256)
void k_final(const float* __restrict__ W3, const float* __restrict__ b3,
             float* __restrict__ out)
{
    __shared__ float w[MID_CH];
    int tid = threadIdx.x;
    if (tid < MID_CH) w[tid] = W3[tid];
    __syncthreads();

    int node = blockIdx.x * 8 + (tid >> 5);
    if (node >= N_NODES) return;
    int lane = tid & 31;

    const float* hrow = g_h2 + (size_t)node * MID_CH;
    float s = 0.0f;
#pragma unroll
    for (int j = 0; j < 8; j++) {
        int c = lane + 32 * j;
        s = fmaf(hrow[c], w[c], s);
    }
#pragma unroll
    for (int o = 16; o > 0; o >>= 1) s += __shfl_down_sync(0xffffffffu, s, o);
    if (lane == 0) out[node] = s + b3[0];
}

// ---------------------------------------------------------------------------
// kernel_launch
// inputs: x[50000,128] f32, edge_index[2,800000] INT32, W_conv[128,128],
//         b_conv[128], W1[128,256], b1[256], W2[256,256], b2[256],
//         W3[256,1], b3[1]
// out:    [50000] fp32
// ---------------------------------------------------------------------------
extern "C" void kernel_launch(void* const* d_in, const int* in_sizes, int n_in,
                              void* d_out, int out_size)
{
    const float* x      = (const float*)d_in[0];
    const int*   eidx   = (const int*)d_in[1];     // int32! (JAX x64 disabled)
    const float* W_conv = (const float*)d_in[2];
    const float* b_conv = (const float*)d_in[3];
    const float* W1     = (const float*)d_in[4];
    const float* b1     = (const float*)d_in[5];
    const float* W2     = (const float*)d_in[6];
    const float* b2     = (const float*)d_in[7];
    const float* W3     = (const float*)d_in[8];
    const float* b3     = (const float*)d_in[9];
    float*       out    = (float*)d_out;

    const int* e_src = eidx;            // edge_index[0]
    const int* e_dst = eidx + N_EDGES;  // edge_index[1]

    // degree + norm
    k_deg_init<<<(N_NODES + 255) / 256, 256>>>();
    k_deg_count<<<(N_EDGES + 255) / 256, 256>>>(e_dst);
    k_dis<<<(N_NODES + 255) / 256, 256>>>();

    // h = x @ W_conv   (bias applied later in epilogue)
    {
        dim3 grid(IN_CH / BN, (N_NODES + BM - 1) / BM);
        k_gemm_conv<<<grid, 256>>>(x, W_conv);
    }

    // agg = selfloop contribution (also initializes g_agg), then edge scatter
    {
        size_t tot = (size_t)N_NODES * IN_CH;
        k_selfloop<<<(unsigned)((tot + 255) / 256), 256>>>();
    }
    k_scatter<<<(N_EDGES + 7) / 8, 256>>>(e_src, e_dst);

    // h = relu(agg + b_conv) + x
    {
        size_t tot = (size_t)N_NODES * IN_CH;
        k_postconv<<<(unsigned)((tot + 255) / 256), 256>>>(x, b_conv);
    }

    // h1 = relu(h @ W1 + b1)
    {
        dim3 grid(MID_CH / BN, (N_NODES + BM - 1) / BM);
        k_gemm_mlp1<<<grid, 256>>>(W1, b1);
    }
    // h2 = relu(h1 @ W2 + b2)
    {
        dim3 grid(MID_CH / BN, (N_NODES + BM - 1) / BM);
        k_gemm_mlp2<<<grid, 256>>>(W2, b2);
    }
    // out = h2 @ W3 + b3
    k_final<<<(N_NODES + 7) / 8, 256>>>(W3, b3, out);
}

// round 6
// speedup vs baseline: 1.6068x; 1.6068x over previous
#include <cuda_runtime.h>
#include <cuda_bf16.h>
#include <cstdint>

// ---------------------------------------------------------------------------
// Problem constants
// ---------------------------------------------------------------------------
#define N_NODES 50000
#define N_EDGES 800000
#define IN_CH   128
#define MID_CH  256

// ---------------------------------------------------------------------------
// Scratch (device globals; no dynamic allocation allowed)
// ---------------------------------------------------------------------------
__device__ __align__(16) float g_deg[N_NODES];
__device__ __align__(16) float g_dis[N_NODES];
__device__ __align__(16) float g_h  [(size_t)N_NODES * IN_CH];
__device__ __align__(16) float g_agg[(size_t)N_NODES * IN_CH];
__device__ __align__(16) float g_h1 [(size_t)N_NODES * MID_CH];
__device__ __align__(16) float g_h2 [(size_t)N_NODES * MID_CH];

// ---------------------------------------------------------------------------
// Degree / norm kernels
// ---------------------------------------------------------------------------
__global__ void k_deg_init()
{
    int i = blockIdx.x * blockDim.x + threadIdx.x;
    if (i < N_NODES) g_deg[i] = 1.0f;
}

__global__ void k_deg_count(const int* __restrict__ dst)
{
    int e = blockIdx.x * blockDim.x + threadIdx.x;
    if (e < N_EDGES) atomicAdd(&g_deg[dst[e]], 1.0f);
}

__global__ void k_dis()
{
    int i = blockIdx.x * blockDim.x + threadIdx.x;
    if (i < N_NODES) g_dis[i] = rsqrtf(g_deg[i]);
}

// ---------------------------------------------------------------------------
// SGEMM: C[M,N] = A[M,K] @ B[K,N] (+bias, +relu)
// BM=BN=128, BK=16, 256 threads, 8x8 microtile, float4 vectorized.
// N, K compile-time multiples of 128/16; M guarded.
// ---------------------------------------------------------------------------
#define BM 128
#define BN 128
#define BK 16
#define TM 8
#define TN 8
#define APAD 4          // pad As rows to kill store bank conflicts

template<int N, int K, bool RELU, bool BIAS>
__device__ __forceinline__
void gemm_body(const float* __restrict__ A, const float* __restrict__ B,
               const float* __restrict__ bias, float* __restrict__ C, int M)
{
    __shared__ float As[BK][BM + APAD];   // transposed A tile
    __shared__ float Bs[BK][BN];

    const int tid  = threadIdx.x;
    const int tr   = tid >> 4;            // 0..15
    const int tc   = tid & 15;            // 0..15
    const int row0 = blockIdx.y * BM;
    const int col0 = blockIdx.x * BN;

    float acc[TM][TN];
#pragma unroll
    for (int i = 0; i < TM; i++)
#pragma unroll
        for (int j = 0; j < TN; j++) acc[i][j] = 0.0f;

#pragma unroll 1
    for (int k0 = 0; k0 < K; k0 += BK) {
        // --- A tile: BM x BK = 512 float4, 2 per thread; store transposed ---
#pragma unroll
        for (int t = 0; t < 2; t++) {
            int f   = tid + t * 256;          // 0..511
            int r   = f >> 2;                 // 0..127
            int c4  = f & 3;                  // 0..3  (k-offset /4)
            int gr  = row0 + r;
            float4 v = make_float4(0.f, 0.f, 0.f, 0.f);
            if (gr < M)
                v = *reinterpret_cast<const float4*>(A + (size_t)gr * K + k0 + c4 * 4);
            As[c4 * 4 + 0][r] = v.x;
            As[c4 * 4 + 1][r] = v.y;
            As[c4 * 4 + 2][r] = v.z;
            As[c4 * 4 + 3][r] = v.w;
        }
        // --- B tile: BK x BN = 512 float4, 2 per thread ---
#pragma unroll
        for (int t = 0; t < 2; t++) {
            int f   = tid + t * 256;
            int r   = f >> 5;                 // 0..15
            int c4  = f & 31;                 // 0..31
            float4 v = *reinterpret_cast<const float4*>(
                B + (size_t)(k0 + r) * N + col0 + c4 * 4);
            *reinterpret_cast<float4*>(&Bs[r][c4 * 4]) = v;
        }
        __syncthreads();

#pragma unroll
        for (int kk = 0; kk < BK; kk++) {
            float a[TM], b[TN];
            *reinterpret_cast<float4*>(&a[0]) =
                *reinterpret_cast<const float4*>(&As[kk][tr * TM + 0]);
            *reinterpret_cast<float4*>(&a[4]) =
                *reinterpret_cast<const float4*>(&As[kk][tr * TM + 4]);
            *reinterpret_cast<float4*>(&b[0]) =
                *reinterpret_cast<const float4*>(&Bs[kk][tc * TN + 0]);
            *reinterpret_cast<float4*>(&b[4]) =
                *reinterpret_cast<const float4*>(&Bs[kk][tc * TN + 4]);
#pragma unroll
            for (int i = 0; i < TM; i++)
#pragma unroll
                for (int j = 0; j < TN; j++)
                    acc[i][j] = fmaf(a[i], b[j], acc[i][j]);
        }
        __syncthreads();
    }

    // --- epilogue: bias/relu + vectorized store ---
#pragma unroll
    for (int i = 0; i < TM; i++) {
        int gr = row0 + tr * TM + i;
        if (gr >= M) continue;
#pragma unroll
        for (int j4 = 0; j4 < TN / 4; j4++) {
            float4 v;
            float* vv = &v.x;
#pragma unroll
            for (int j = 0; j < 4; j++) {
                int gc = col0 + tc * TN + j4 * 4 + j;
                float t = acc[i][j4 * 4 + j];
                if (BIAS) t += bias[gc];
                if (RELU) t = fmaxf(t, 0.0f);
                vv[j] = t;
            }
            *reinterpret_cast<float4*>(C + (size_t)gr * N + col0 + tc * TN + j4 * 4) = v;
        }
    }
}

__global__ __launch_bounds__(256)
void k_gemm_conv(const float* __restrict__ x, const float* __restrict__ W)
{
    gemm_body<IN_CH, IN_CH, false, false>(x, W, nullptr, g_h, N_NODES);
}

__global__ __launch_bounds__(256)
void k_gemm_mlp1(const float* __restrict__ W1, const float* __restrict__ b1)
{
    gemm_body<MID_CH, IN_CH, true, true>(g_h, W1, b1, g_h1, N_NODES);
}

__global__ __launch_bounds__(256)
void k_gemm_mlp2(const float* __restrict__ W2, const float* __restrict__ b2)
{
    gemm_body<MID_CH, MID_CH, true, true>(g_h1, W2, b2, g_h2, N_NODES);
}

// ---------------------------------------------------------------------------
// Self-loop (also initializes g_agg): agg[i,:] = dis[i]^2 * h[i,:]
// float4: 1.6M vec elements
// ---------------------------------------------------------------------------
__global__ void k_selfloop()
{
    size_t i = (size_t)blockIdx.x * blockDim.x + threadIdx.x;   // float4 index
    if (i >= (size_t)N_NODES * IN_CH / 4) return;
    int node = (int)(i >> 5);                                    // /(128/4)
    float d  = g_dis[node];
    float s  = d * d;
    float4 v = reinterpret_cast<const float4*>(g_h)[i];
    v.x *= s; v.y *= s; v.z *= s; v.w *= s;
    reinterpret_cast<float4*>(g_agg)[i] = v;
}

// ---------------------------------------------------------------------------
// Edge scatter: agg[dst,:] += dis[src]*dis[dst] * h[src,:]
// One warp per edge, lane = 4 channels, vector RED (red.global.add.v4.f32).
// ---------------------------------------------------------------------------
__global__ __launch_bounds__(256)
void k_scatter(const int* __restrict__ src, const int* __restrict__ dst)
{
    int e = blockIdx.x * 8 + (threadIdx.x >> 5);
    if (e >= N_EDGES) return;
    int lane = threadIdx.x & 31;

    int s = __ldg(src + e);
    int d = __ldg(dst + e);
    float nrm = g_dis[s] * g_dis[d];

    float4 v = reinterpret_cast<const float4*>(g_h + (size_t)s * IN_CH)[lane];
    v.x *= nrm; v.y *= nrm; v.z *= nrm; v.w *= nrm;

    float* ag = g_agg + (size_t)d * IN_CH + lane * 4;
    asm volatile("red.global.add.v4.f32 [%0], {%1, %2, %3, %4};"
                 :: "l"(ag), "f"(v.x), "f"(v.y), "f"(v.z), "f"(v.w)
                 : "memory");
}

// ---------------------------------------------------------------------------
// Post-conv epilogue: h = relu(agg + b_conv) + x   (float4)
// ---------------------------------------------------------------------------
__global__ void k_postconv(const float* __restrict__ x, const float* __restrict__ b_conv)
{
    size_t i = (size_t)blockIdx.x * blockDim.x + threadIdx.x;   // float4 index
    if (i >= (size_t)N_NODES * IN_CH / 4) return;
    int c4 = (int)(i & 31);                                      // float4 within row
    float4 b  = reinterpret_cast<const float4*>(b_conv)[c4];
    float4 a  = reinterpret_cast<const float4*>(g_agg)[i];
    float4 xr = reinterpret_cast<const float4*>(x)[i];
    float4 o;
    o.x = fmaxf(a.x + b.x, 0.0f) + xr.x;
    o.y = fmaxf(a.y + b.y, 0.0f) + xr.y;
    o.z = fmaxf(a.z + b.z, 0.0f) + xr.z;
    o.w = fmaxf(a.w + b.w, 0.0f) + xr.w;
    reinterpret_cast<float4*>(g_h)[i] = o;
}

// ---------------------------------------------------------------------------
// Final layer: out[i] = dot(h2[i,:], W3) + b3
// One warp per node, float4 loads.
// ---------------------------------------------------------------------------
__global__ __launch_bounds__(256)
void k_final(const float* __restrict__ W3, const float* __restrict__ b3,
             float* __restrict__ out)
{
    __shared__ float w[MID_CH];
    int tid = threadIdx.x;
    if (tid < MID_CH) w[tid] = W3[tid];
    __syncthreads();

    int node = blockIdx.x * 8 + (tid >> 5);
    if (node >= N_NODES) return;
    int lane = tid & 31;

    const float4* hrow = reinterpret_cast<const float4*>(g_h2 + (size_t)node * MID_CH);
    const float4* wv   = reinterpret_cast<const float4*>(w);

    float s = 0.0f;
#pragma unroll
    for (int j = 0; j < 2; j++) {
        int c = lane + 32 * j;
        float4 h4 = hrow[c];
        float4 w4 = wv[c];
        s = fmaf(h4.x, w4.x, s);
        s = fmaf(h4.y, w4.y, s);
        s = fmaf(h4.z, w4.z, s);
        s = fmaf(h4.w, w4.w, s);
    }
#pragma unroll
    for (int o = 16; o > 0; o >>= 1) s += __shfl_down_sync(0xffffffffu, s, o);
    if (lane == 0) out[node] = s + b3[0];
}

// ---------------------------------------------------------------------------
// kernel_launch
// inputs: x[50000,128] f32, edge_index[2,800000] int32, W_conv[128,128],
//         b_conv[128], W1[128,256], b1[256], W2[256,256], b2[256],
//         W3[256,1], b3[1]   -> out [50000] f32
// ---------------------------------------------------------------------------
extern "C" void kernel_launch(void* const* d_in, const int* in_sizes, int n_in,
                              void* d_out, int out_size)
{
    const float* x      = (const float*)d_in[0];
    const int*   eidx   = (const int*)d_in[1];     // int32 (JAX x64 disabled)
    const float* W_conv = (const float*)d_in[2];
    const float* b_conv = (const float*)d_in[3];
    const float* W1     = (const float*)d_in[4];
    const float* b1     = (const float*)d_in[5];
    const float* W2     = (const float*)d_in[6];
    const float* b2     = (const float*)d_in[7];
    const float* W3     = (const float*)d_in[8];
    const float* b3     = (const float*)d_in[9];
    float*       out    = (float*)d_out;

    const int* e_src = eidx;
    const int* e_dst = eidx + N_EDGES;

    k_deg_init<<<(N_NODES + 255) / 256, 256>>>();
    k_deg_count<<<(N_EDGES + 255) / 256, 256>>>(e_dst);
    k_dis<<<(N_NODES + 255) / 256, 256>>>();

    // h = x @ W_conv
    {
        dim3 grid(IN_CH / BN, (N_NODES + BM - 1) / BM);
        k_gemm_conv<<<grid, 256>>>(x, W_conv);
    }

    // agg = selfloop + edges
    {
        size_t tot4 = (size_t)N_NODES * IN_CH / 4;
        k_selfloop<<<(unsigned)((tot4 + 255) / 256), 256>>>();
    }
    k_scatter<<<(N_EDGES + 7) / 8, 256>>>(e_src, e_dst);

    // h = relu(agg + b_conv) + x
    {
        size_t tot4 = (size_t)N_NODES * IN_CH / 4;
        k_postconv<<<(unsigned)((tot4 + 255) / 256), 256>>>(x, b_conv);
    }

    // h1 = relu(h @ W1 + b1)
    {
        dim3 grid(MID_CH / BN, (N_NODES + BM - 1) / BM);
        k_gemm_mlp1<<<grid, 256>>>(W1, b1);
    }
    // h2 = relu(h1 @ W2 + b2)
    {
        dim3 grid(MID_CH / BN, (N_NODES + BM - 1) / BM);
        k_gemm_mlp2<<<grid, 256>>>(W2, b2);
    }
    // out = h2 @ W3 + b3
    k_final<<<(N_NODES + 7) / 8, 256>>>(W3, b3, out);
}

// round 7
// speedup vs baseline: 2.9375x; 1.8281x over previous
#include <cuda_runtime.h>
#include <cuda_bf16.h>
#include <cstdint>

// ---------------------------------------------------------------------------
// Problem constants
// ---------------------------------------------------------------------------
#define N_NODES 50000
#define N_EDGES 800000
#define IN_CH   128
#define MID_CH  256

// ---------------------------------------------------------------------------
// Scratch (device globals; no dynamic allocation allowed)
// ---------------------------------------------------------------------------
__device__ __align__(16) float g_deg[N_NODES];
__device__ __align__(16) float g_dis[N_NODES];
__device__ __align__(16) float g_h  [(size_t)N_NODES * IN_CH];
__device__ __align__(16) float g_agg[(size_t)N_NODES * IN_CH];
__device__ __align__(16) float g_h1 [(size_t)N_NODES * MID_CH];
__device__ __align__(16) float g_h2 [(size_t)N_NODES * MID_CH];

// ---------------------------------------------------------------------------
// Degree / norm kernels
// ---------------------------------------------------------------------------
__global__ void k_deg_init()
{
    int i = blockIdx.x * blockDim.x + threadIdx.x;
    if (i < N_NODES) g_deg[i] = 1.0f;
}

__global__ void k_deg_count(const int* __restrict__ dst)
{
    int e = blockIdx.x * blockDim.x + threadIdx.x;
    if (e < N_EDGES) atomicAdd(&g_deg[dst[e]], 1.0f);
}

__global__ void k_dis()
{
    int i = blockIdx.x * blockDim.x + threadIdx.x;
    if (i < N_NODES) g_dis[i] = rsqrtf(g_deg[i]);
}

// ---------------------------------------------------------------------------
// TF32 tensor-core GEMM: C[M,N] = A[M,K] @ B[K,N] (+bias, +relu)
// BM=BN=128, BK=32, 256 threads = 8 warps (2 x 4), warp tile 64x32,
// mma.sync.aligned.m16n8k8.row.col.f32.tf32.tf32.f32.
// Inputs converted to tf32 (cvt.rna) at the global->smem stage.
// Smem padding: As rows +4 floats -> A-frag banks = (4g+tig) perm (conflict-free)
//               Bs rows +8 floats -> B-frag banks = (8t+g) perm (conflict-free)
// ---------------------------------------------------------------------------
#define BM 128
#define BN 128
#define BK 32
#define APAD 4
#define BPAD 8

__device__ __forceinline__ float f2tf32(float x)
{
    uint32_t u;
    asm("cvt.rna.tf32.f32 %0, %1;" : "=r"(u) : "f"(x));
    return __uint_as_float(u);
}

template<int N, int K, bool RELU, bool BIAS>
__device__ __forceinline__
void gemm_body(const float* __restrict__ A, const float* __restrict__ B,
               const float* __restrict__ bias, float* __restrict__ C, int M)
{
    __shared__ float As[BM][BK + APAD];   // row-major M x K
    __shared__ float Bs[BK][BN + BPAD];   // row-major K x N

    const int tid  = threadIdx.x;
    const int wid  = tid >> 5;
    const int lane = tid & 31;
    const int g    = lane >> 2;   // groupID 0..7
    const int t    = lane & 3;    // threadID_in_group 0..3

    const int warp_m = wid & 1;   // 0..1  -> 64-row slab
    const int warp_n = wid >> 1;  // 0..3  -> 32-col slab

    const int row0 = blockIdx.y * BM;
    const int col0 = blockIdx.x * BN;

    float acc[4][4][4];           // [m-tile][n-tile][c0..c3]
#pragma unroll
    for (int i = 0; i < 4; i++)
#pragma unroll
        for (int j = 0; j < 4; j++)
#pragma unroll
            for (int r = 0; r < 4; r++) acc[i][j][r] = 0.0f;

#pragma unroll 1
    for (int k0 = 0; k0 < K; k0 += BK) {
        // --- A tile: 128x32 = 1024 float4, 4 per thread (tf32 convert) ---
#pragma unroll
        for (int it = 0; it < 4; it++) {
            int idx = tid + it * 256;        // 0..1023
            int r   = idx >> 3;              // 8 float4 per 32-float row
            int c4  = idx & 7;
            int gr  = row0 + r;
            float4 v = make_float4(0.f, 0.f, 0.f, 0.f);
            if (gr < M)
                v = *reinterpret_cast<const float4*>(A + (size_t)gr * K + k0 + c4 * 4);
            float* dstp = &As[r][c4 * 4];
            dstp[0] = f2tf32(v.x); dstp[1] = f2tf32(v.y);
            dstp[2] = f2tf32(v.z); dstp[3] = f2tf32(v.w);
        }
        // --- B tile: 32x128 = 1024 float4, 4 per thread (tf32 convert) ---
#pragma unroll
        for (int it = 0; it < 4; it++) {
            int idx = tid + it * 256;
            int r   = idx >> 5;              // 32 float4 per 128-float row
            int c4  = idx & 31;
            float4 v = *reinterpret_cast<const float4*>(
                B + (size_t)(k0 + r) * N + col0 + c4 * 4);
            float* dstp = &Bs[r][c4 * 4];
            dstp[0] = f2tf32(v.x); dstp[1] = f2tf32(v.y);
            dstp[2] = f2tf32(v.z); dstp[3] = f2tf32(v.w);
        }
        __syncthreads();

#pragma unroll
        for (int kk = 0; kk < BK; kk += 8) {
            // load fragments
            uint32_t af[4][4];
#pragma unroll
            for (int mt = 0; mt < 4; mt++) {
                int rb = warp_m * 64 + mt * 16;
                af[mt][0] = __float_as_uint(As[rb + g    ][kk + t    ]);
                af[mt][1] = __float_as_uint(As[rb + g + 8][kk + t    ]);
                af[mt][2] = __float_as_uint(As[rb + g    ][kk + t + 4]);
                af[mt][3] = __float_as_uint(As[rb + g + 8][kk + t + 4]);
            }
            uint32_t bf[4][2];
#pragma unroll
            for (int nt = 0; nt < 4; nt++) {
                int cb = warp_n * 32 + nt * 8 + g;
                bf[nt][0] = __float_as_uint(Bs[kk + t    ][cb]);
                bf[nt][1] = __float_as_uint(Bs[kk + t + 4][cb]);
            }
#pragma unroll
            for (int mt = 0; mt < 4; mt++)
#pragma unroll
                for (int nt = 0; nt < 4; nt++) {
                    asm volatile(
                        "mma.sync.aligned.m16n8k8.row.col.f32.tf32.tf32.f32 "
                        "{%0,%1,%2,%3}, {%4,%5,%6,%7}, {%8,%9}, {%0,%1,%2,%3};"
                        : "+f"(acc[mt][nt][0]), "+f"(acc[mt][nt][1]),
                          "+f"(acc[mt][nt][2]), "+f"(acc[mt][nt][3])
                        : "r"(af[mt][0]), "r"(af[mt][1]),
                          "r"(af[mt][2]), "r"(af[mt][3]),
                          "r"(bf[nt][0]), "r"(bf[nt][1]));
                }
        }
        __syncthreads();
    }

    // --- epilogue: c0/c1 -> (row=g, cols 2t,2t+1), c2/c3 -> row=g+8 ---
#pragma unroll
    for (int mt = 0; mt < 4; mt++) {
#pragma unroll
        for (int half = 0; half < 2; half++) {
            int gr = row0 + warp_m * 64 + mt * 16 + g + half * 8;
            if (gr >= M) continue;
#pragma unroll
            for (int nt = 0; nt < 4; nt++) {
                int gc = col0 + warp_n * 32 + nt * 8 + t * 2;
                float v0 = acc[mt][nt][half * 2 + 0];
                float v1 = acc[mt][nt][half * 2 + 1];
                if (BIAS) { v0 += bias[gc]; v1 += bias[gc + 1]; }
                if (RELU) { v0 = fmaxf(v0, 0.0f); v1 = fmaxf(v1, 0.0f); }
                *reinterpret_cast<float2*>(C + (size_t)gr * N + gc) =
                    make_float2(v0, v1);
            }
        }
    }
}

__global__ __launch_bounds__(256)
void k_gemm_conv(const float* __restrict__ x, const float* __restrict__ W)
{
    gemm_body<IN_CH, IN_CH, false, false>(x, W, nullptr, g_h, N_NODES);
}

__global__ __launch_bounds__(256)
void k_gemm_mlp1(const float* __restrict__ W1, const float* __restrict__ b1)
{
    gemm_body<MID_CH, IN_CH, true, true>(g_h, W1, b1, g_h1, N_NODES);
}

__global__ __launch_bounds__(256)
void k_gemm_mlp2(const float* __restrict__ W2, const float* __restrict__ b2)
{
    gemm_body<MID_CH, MID_CH, true, true>(g_h1, W2, b2, g_h2, N_NODES);
}

// ---------------------------------------------------------------------------
// Self-loop (also initializes g_agg): agg[i,:] = dis[i]^2 * h[i,:]
// ---------------------------------------------------------------------------
__global__ void k_selfloop()
{
    size_t i = (size_t)blockIdx.x * blockDim.x + threadIdx.x;   // float4 index
    if (i >= (size_t)N_NODES * IN_CH / 4) return;
    int node = (int)(i >> 5);
    float d  = g_dis[node];
    float s  = d * d;
    float4 v = reinterpret_cast<const float4*>(g_h)[i];
    v.x *= s; v.y *= s; v.z *= s; v.w *= s;
    reinterpret_cast<float4*>(g_agg)[i] = v;
}

// ---------------------------------------------------------------------------
// Edge scatter: agg[dst,:] += dis[src]*dis[dst] * h[src,:]
// One warp per edge, lane = 4 channels, vector RED.
// ---------------------------------------------------------------------------
__global__ __launch_bounds__(256)
void k_scatter(const int* __restrict__ src, const int* __restrict__ dst)
{
    int e = blockIdx.x * 8 + (threadIdx.x >> 5);
    if (e >= N_EDGES) return;
    int lane = threadIdx.x & 31;

    int s = __ldg(src + e);
    int d = __ldg(dst + e);
    float nrm = g_dis[s] * g_dis[d];

    float4 v = reinterpret_cast<const float4*>(g_h + (size_t)s * IN_CH)[lane];
    v.x *= nrm; v.y *= nrm; v.z *= nrm; v.w *= nrm;

    float* ag = g_agg + (size_t)d * IN_CH + lane * 4;
    asm volatile("red.global.add.v4.f32 [%0], {%1, %2, %3, %4};"
                 :: "l"(ag), "f"(v.x), "f"(v.y), "f"(v.z), "f"(v.w)
                 : "memory");
}

// ---------------------------------------------------------------------------
// Post-conv epilogue: h = relu(agg + b_conv) + x
// ---------------------------------------------------------------------------
__global__ void k_postconv(const float* __restrict__ x, const float* __restrict__ b_conv)
{
    size_t i = (size_t)blockIdx.x * blockDim.x + threadIdx.x;   // float4 index
    if (i >= (size_t)N_NODES * IN_CH / 4) return;
    int c4 = (int)(i & 31);
    float4 b  = reinterpret_cast<const float4*>(b_conv)[c4];
    float4 a  = reinterpret_cast<const float4*>(g_agg)[i];
    float4 xr = reinterpret_cast<const float4*>(x)[i];
    float4 o;
    o.x = fmaxf(a.x + b.x, 0.0f) + xr.x;
    o.y = fmaxf(a.y + b.y, 0.0f) + xr.y;
    o.z = fmaxf(a.z + b.z, 0.0f) + xr.z;
    o.w = fmaxf(a.w + b.w, 0.0f) + xr.w;
    reinterpret_cast<float4*>(g_h)[i] = o;
}

// ---------------------------------------------------------------------------
// Final layer: out[i] = dot(h2[i,:], W3) + b3
// ---------------------------------------------------------------------------
__global__ __launch_bounds__(256)
void k_final(const float* __restrict__ W3, const float* __restrict__ b3,
             float* __restrict__ out)
{
    __shared__ float w[MID_CH];
    int tid = threadIdx.x;
    if (tid < MID_CH) w[tid] = W3[tid];
    __syncthreads();

    int node = blockIdx.x * 8 + (tid >> 5);
    if (node >= N_NODES) return;
    int lane = tid & 31;

    const float4* hrow = reinterpret_cast<const float4*>(g_h2 + (size_t)node * MID_CH);
    const float4* wv   = reinterpret_cast<const float4*>(w);

    float s = 0.0f;
#pragma unroll
    for (int j = 0; j < 2; j++) {
        int c = lane + 32 * j;
        float4 h4 = hrow[c];
        float4 w4 = wv[c];
        s = fmaf(h4.x, w4.x, s);
        s = fmaf(h4.y, w4.y, s);
        s = fmaf(h4.z, w4.z, s);
        s = fmaf(h4.w, w4.w, s);
    }
#pragma unroll
    for (int o = 16; o > 0; o >>= 1) s += __shfl_down_sync(0xffffffffu, s, o);
    if (lane == 0) out[node] = s + b3[0];
}

// ---------------------------------------------------------------------------
// kernel_launch
// ---------------------------------------------------------------------------
extern "C" void kernel_launch(void* const* d_in, const int* in_sizes, int n_in,
                              void* d_out, int out_size)
{
    const float* x      = (const float*)d_in[0];
    const int*   eidx   = (const int*)d_in[1];     // int32 (JAX x64 disabled)
    const float* W_conv = (const float*)d_in[2];
    const float* b_conv = (const float*)d_in[3];
    const float* W1     = (const float*)d_in[4];
    const float* b1     = (const float*)d_in[5];
    const float* W2     = (const float*)d_in[6];
    const float* b2     = (const float*)d_in[7];
    const float* W3     = (const float*)d_in[8];
    const float* b3     = (const float*)d_in[9];
    float*       out    = (float*)d_out;

    const int* e_src = eidx;
    const int* e_dst = eidx + N_EDGES;

    k_deg_init<<<(N_NODES + 255) / 256, 256>>>();
    k_deg_count<<<(N_EDGES + 255) / 256, 256>>>(e_dst);
    k_dis<<<(N_NODES + 255) / 256, 256>>>();

    // h = x @ W_conv
    {
        dim3 grid(IN_CH / BN, (N_NODES + BM - 1) / BM);
        k_gemm_conv<<<grid, 256>>>(x, W_conv);
    }

    // agg = selfloop + edges
    {
        size_t tot4 = (size_t)N_NODES * IN_CH / 4;
        k_selfloop<<<(unsigned)((tot4 + 255) / 256), 256>>>();
    }
    k_scatter<<<(N_EDGES + 7) / 8, 256>>>(e_src, e_dst);

    // h = relu(agg + b_conv) + x
    {
        size_t tot4 = (size_t)N_NODES * IN_CH / 4;
        k_postconv<<<(unsigned)((tot4 + 255) / 256), 256>>>(x, b_conv);
    }

    // h1 = relu(h @ W1 + b1)
    {
        dim3 grid(MID_CH / BN, (N_NODES + BM - 1) / BM);
        k_gemm_mlp1<<<grid, 256>>>(W1, b1);
    }
    // h2 = relu(h1 @ W2 + b2)
    {
        dim3 grid(MID_CH / BN, (N_NODES + BM - 1) / BM);
        k_gemm_mlp2<<<grid, 256>>>(W2, b2);
    }
    // out = h2 @ W3 + b3
    k_final<<<(N_NODES + 7) / 8, 256>>>(W3, b3, out);
}

// round 8
// speedup vs baseline: 3.2202x; 1.0963x over previous
#include <cuda_runtime.h>
#include <cuda_bf16.h>
#include <cstdint>

// ---------------------------------------------------------------------------
// Problem constants
// ---------------------------------------------------------------------------
#define N_NODES 50000
#define N_EDGES 800000
#define IN_CH   128
#define MID_CH  256

// ---------------------------------------------------------------------------
// Scratch (device globals; no dynamic allocation allowed)
// ---------------------------------------------------------------------------
__device__ __align__(16) float g_deg[N_NODES];
__device__ __align__(16) float g_dis[N_NODES];
__device__ __align__(16) float g_h  [(size_t)N_NODES * IN_CH];
__device__ __align__(16) float g_agg[(size_t)N_NODES * IN_CH];
__device__ __align__(16) float g_h1 [(size_t)N_NODES * MID_CH];

// ---------------------------------------------------------------------------
// Degree / norm kernels
// ---------------------------------------------------------------------------
__global__ void k_deg_init()
{
    int i = blockIdx.x * blockDim.x + threadIdx.x;
    if (i < N_NODES) g_deg[i] = 1.0f;
}

__global__ void k_deg_count(const int* __restrict__ dst)
{
    int e = blockIdx.x * blockDim.x + threadIdx.x;
    if (e < N_EDGES) atomicAdd(&g_deg[dst[e]], 1.0f);
}

__global__ void k_dis()
{
    int i = blockIdx.x * blockDim.x + threadIdx.x;
    if (i < N_NODES) g_dis[i] = rsqrtf(g_deg[i]);
}

__global__ void k_out_init(float* __restrict__ out, const float* __restrict__ b3)
{
    int i = blockIdx.x * blockDim.x + threadIdx.x;
    if (i < N_NODES) out[i] = b3[0];
}

// ---------------------------------------------------------------------------
// TF32 tensor-core GEMM, cp.async double-buffered.
// BM=BN=128, BK=32, 256 threads = 8 warps (2 x 4), warp tile 64x32,
// mma.sync.aligned.m16n8k8. Raw fp32 copied via cp.async; cvt.rna at
// fragment load. Dynamic smem = 2*(As + Bs) = 71680 B.
// EPI modes: 0 = plain store (+bias/relu), 1 = conv (store h AND agg=dis^2*h),
//            2 = fused final (relu(acc+bias) dot W3 -> RED to out).
// ---------------------------------------------------------------------------
#define BM 128
#define BN 128
#define BK 32
#define APAD 4
#define BPAD 8

#define AS_STRIDE (BK + APAD)            // 36 floats (144 B, 16B-aligned rows)
#define BS_STRIDE (BN + BPAD)            // 136 floats (544 B, 16B-aligned rows)
#define AS_ELEMS  (BM * AS_STRIDE)       // per buffer
#define BS_ELEMS  (BK * BS_STRIDE)
#define GEMM_SMEM_BYTES ((2 * AS_ELEMS + 2 * BS_ELEMS) * 4)   // 71680

__device__ __forceinline__ uint32_t tf32r(float x)
{
    uint32_t u;
    asm("cvt.rna.tf32.f32 %0, %1;" : "=r"(u) : "f"(x));
    return u;
}

__device__ __forceinline__ void cp_async16(float* smem_dst, const float* gsrc, bool pred)
{
    uint32_t saddr = (uint32_t)__cvta_generic_to_shared(smem_dst);
    int sz = pred ? 16 : 0;
    asm volatile("cp.async.cg.shared.global [%0], [%1], 16, %2;"
                 :: "r"(saddr), "l"(gsrc), "r"(sz));
}

template<int N, int K, int EPI, bool RELU, bool BIAS>
__device__ __forceinline__
void gemm_body(const float* __restrict__ A, const float* __restrict__ B,
               const float* __restrict__ bias, float* __restrict__ C,
               const float* __restrict__ W3, float* __restrict__ out, int M)
{
    extern __shared__ float smem[];
    float* As = smem;                          // [2][BM][AS_STRIDE]
    float* Bs = smem + 2 * AS_ELEMS;           // [2][BK][BS_STRIDE]

    const int tid  = threadIdx.x;
    const int wid  = tid >> 5;
    const int lane = tid & 31;
    const int g    = lane >> 2;   // 0..7
    const int t    = lane & 3;    // 0..3

    const int warp_m = wid & 1;
    const int warp_n = wid >> 1;

    const int row0 = blockIdx.y * BM;
    const int col0 = blockIdx.x * BN;

    // per-thread load coordinates (constant across tiles)
    const int a_r  = tid >> 3;               // row within BM half? no: see below
    // A tile: 128x32 floats = 1024 float4; thread handles 4 float4:
    //   idx = tid + it*256; r = idx>>3 (0..127), c4 = idx&7
    // B tile: 32x128 floats = 1024 float4:
    //   idx = tid + it*256; r = idx>>5 (0..31), c4 = idx&31
    (void)a_r;

    float acc[4][4][4];
#pragma unroll
    for (int i = 0; i < 4; i++)
#pragma unroll
        for (int j = 0; j < 4; j++)
#pragma unroll
            for (int r = 0; r < 4; r++) acc[i][j][r] = 0.0f;

    const int NT = K / BK;

    // ---- prefetch tile 0 ----
    {
        float* Ab = As;           // buffer 0
        float* Bb = Bs;
#pragma unroll
        for (int it = 0; it < 4; it++) {
            int idx = tid + it * 256;
            int r = idx >> 3, c4 = idx & 7;
            int gr = row0 + r;
            const float* src = A + (size_t)(gr < M ? gr : 0) * K + c4 * 4;
            cp_async16(&Ab[r * AS_STRIDE + c4 * 4], src, gr < M);
        }
#pragma unroll
        for (int it = 0; it < 4; it++) {
            int idx = tid + it * 256;
            int r = idx >> 5, c4 = idx & 31;
            cp_async16(&Bb[r * BS_STRIDE + c4 * 4],
                       B + (size_t)r * N + col0 + c4 * 4, true);
        }
        asm volatile("cp.async.commit_group;");
    }

#pragma unroll 1
    for (int kt = 0; kt < NT; kt++) {
        asm volatile("cp.async.wait_group 0;");
        __syncthreads();

        // prefetch next tile into other buffer
        if (kt + 1 < NT) {
            int k0 = (kt + 1) * BK;
            float* Ab = As + ((kt + 1) & 1) * AS_ELEMS;
            float* Bb = Bs + ((kt + 1) & 1) * BS_ELEMS;
#pragma unroll
            for (int it = 0; it < 4; it++) {
                int idx = tid + it * 256;
                int r = idx >> 3, c4 = idx & 7;
                int gr = row0 + r;
                const float* src = A + (size_t)(gr < M ? gr : 0) * K + k0 + c4 * 4;
                cp_async16(&Ab[r * AS_STRIDE + c4 * 4], src, gr < M);
            }
#pragma unroll
            for (int it = 0; it < 4; it++) {
                int idx = tid + it * 256;
                int r = idx >> 5, c4 = idx & 31;
                cp_async16(&Bb[r * BS_STRIDE + c4 * 4],
                           B + (size_t)(k0 + r) * N + col0 + c4 * 4, true);
            }
            asm volatile("cp.async.commit_group;");
        }

        // compute current buffer
        const float* Ab = As + (kt & 1) * AS_ELEMS;
        const float* Bb = Bs + (kt & 1) * BS_ELEMS;

#pragma unroll
        for (int kk = 0; kk < BK; kk += 8) {
            uint32_t af[4][4];
#pragma unroll
            for (int mt = 0; mt < 4; mt++) {
                int rb = warp_m * 64 + mt * 16;
                af[mt][0] = tf32r(Ab[(rb + g    ) * AS_STRIDE + kk + t    ]);
                af[mt][1] = tf32r(Ab[(rb + g + 8) * AS_STRIDE + kk + t    ]);
                af[mt][2] = tf32r(Ab[(rb + g    ) * AS_STRIDE + kk + t + 4]);
                af[mt][3] = tf32r(Ab[(rb + g + 8) * AS_STRIDE + kk + t + 4]);
            }
            uint32_t bf[4][2];
#pragma unroll
            for (int nt = 0; nt < 4; nt++) {
                int cb = warp_n * 32 + nt * 8 + g;
                bf[nt][0] = tf32r(Bb[(kk + t    ) * BS_STRIDE + cb]);
                bf[nt][1] = tf32r(Bb[(kk + t + 4) * BS_STRIDE + cb]);
            }
#pragma unroll
            for (int mt = 0; mt < 4; mt++)
#pragma unroll
                for (int nt = 0; nt < 4; nt++) {
                    asm volatile(
                        "mma.sync.aligned.m16n8k8.row.col.f32.tf32.tf32.f32 "
                        "{%0,%1,%2,%3}, {%4,%5,%6,%7}, {%8,%9}, {%0,%1,%2,%3};"
                        : "+f"(acc[mt][nt][0]), "+f"(acc[mt][nt][1]),
                          "+f"(acc[mt][nt][2]), "+f"(acc[mt][nt][3])
                        : "r"(af[mt][0]), "r"(af[mt][1]),
                          "r"(af[mt][2]), "r"(af[mt][3]),
                          "r"(bf[nt][0]), "r"(bf[nt][1]));
                }
        }
        __syncthreads();
    }

    // ---- epilogue ----
#pragma unroll
    for (int mt = 0; mt < 4; mt++) {
#pragma unroll
        for (int half = 0; half < 2; half++) {
            int gr = row0 + warp_m * 64 + mt * 16 + g + half * 8;
            if (gr >= M) continue;

            if (EPI == 2) {
                // fused final: s = sum relu(acc+bias)*W3 -> RED to out[gr]
                float s = 0.0f;
#pragma unroll
                for (int nt = 0; nt < 4; nt++) {
                    int gc = col0 + warp_n * 32 + nt * 8 + t * 2;
                    float v0 = acc[mt][nt][half * 2 + 0] + bias[gc];
                    float v1 = acc[mt][nt][half * 2 + 1] + bias[gc + 1];
                    v0 = fmaxf(v0, 0.0f);
                    v1 = fmaxf(v1, 0.0f);
                    s = fmaf(v0, __ldg(W3 + gc), s);
                    s = fmaf(v1, __ldg(W3 + gc + 1), s);
                }
                atomicAdd(out + gr, s);
            } else if (EPI == 1) {
                // conv: store h and agg = dis^2 * h
                float dsq = g_dis[gr];
                dsq = dsq * dsq;
#pragma unroll
                for (int nt = 0; nt < 4; nt++) {
                    int gc = col0 + warp_n * 32 + nt * 8 + t * 2;
                    float v0 = acc[mt][nt][half * 2 + 0];
                    float v1 = acc[mt][nt][half * 2 + 1];
                    *reinterpret_cast<float2*>(C + (size_t)gr * N + gc) =
                        make_float2(v0, v1);
                    *reinterpret_cast<float2*>(g_agg + (size_t)gr * N + gc) =
                        make_float2(dsq * v0, dsq * v1);
                }
            } else {
#pragma unroll
                for (int nt = 0; nt < 4; nt++) {
                    int gc = col0 + warp_n * 32 + nt * 8 + t * 2;
                    float v0 = acc[mt][nt][half * 2 + 0];
                    float v1 = acc[mt][nt][half * 2 + 1];
                    if (BIAS) { v0 += bias[gc]; v1 += bias[gc + 1]; }
                    if (RELU) { v0 = fmaxf(v0, 0.0f); v1 = fmaxf(v1, 0.0f); }
                    *reinterpret_cast<float2*>(C + (size_t)gr * N + gc) =
                        make_float2(v0, v1);
                }
            }
        }
    }
}

__global__ __launch_bounds__(256)
void k_gemm_conv(const float* __restrict__ x, const float* __restrict__ W)
{
    gemm_body<IN_CH, IN_CH, 1, false, false>(x, W, nullptr, g_h, nullptr, nullptr, N_NODES);
}

__global__ __launch_bounds__(256)
void k_gemm_mlp1(const float* __restrict__ W1, const float* __restrict__ b1)
{
    gemm_body<MID_CH, IN_CH, 0, true, true>(g_h, W1, b1, g_h1, nullptr, nullptr, N_NODES);
}

__global__ __launch_bounds__(256)
void k_gemm_mlp2(const float* __restrict__ W2, const float* __restrict__ b2,
                 const float* __restrict__ W3, float* __restrict__ out)
{
    gemm_body<MID_CH, MID_CH, 2, true, true>(g_h1, W2, b2, nullptr, W3, out, N_NODES);
}

// ---------------------------------------------------------------------------
// Edge scatter: agg[dst,:] += dis[src]*dis[dst] * h[src,:]
// One warp per edge, lane = 4 channels, vector RED.
// ---------------------------------------------------------------------------
__global__ __launch_bounds__(256)
void k_scatter(const int* __restrict__ src, const int* __restrict__ dst)
{
    int e = blockIdx.x * 8 + (threadIdx.x >> 5);
    if (e >= N_EDGES) return;
    int lane = threadIdx.x & 31;

    int s = __ldg(src + e);
    int d = __ldg(dst + e);
    float nrm = g_dis[s] * g_dis[d];

    float4 v = reinterpret_cast<const float4*>(g_h + (size_t)s * IN_CH)[lane];
    v.x *= nrm; v.y *= nrm; v.z *= nrm; v.w *= nrm;

    float* ag = g_agg + (size_t)d * IN_CH + lane * 4;
    asm volatile("red.global.add.v4.f32 [%0], {%1, %2, %3, %4};"
                 :: "l"(ag), "f"(v.x), "f"(v.y), "f"(v.z), "f"(v.w)
                 : "memory");
}

// ---------------------------------------------------------------------------
// Post-conv epilogue: h = relu(agg + b_conv) + x
// ---------------------------------------------------------------------------
__global__ void k_postconv(const float* __restrict__ x, const float* __restrict__ b_conv)
{
    size_t i = (size_t)blockIdx.x * blockDim.x + threadIdx.x;   // float4 index
    if (i >= (size_t)N_NODES * IN_CH / 4) return;
    int c4 = (int)(i & 31);
    float4 b  = reinterpret_cast<const float4*>(b_conv)[c4];
    float4 a  = reinterpret_cast<const float4*>(g_agg)[i];
    float4 xr = reinterpret_cast<const float4*>(x)[i];
    float4 o;
    o.x = fmaxf(a.x + b.x, 0.0f) + xr.x;
    o.y = fmaxf(a.y + b.y, 0.0f) + xr.y;
    o.z = fmaxf(a.z + b.z, 0.0f) + xr.z;
    o.w = fmaxf(a.w + b.w, 0.0f) + xr.w;
    reinterpret_cast<float4*>(g_h)[i] = o;
}

// ---------------------------------------------------------------------------
// kernel_launch
// ---------------------------------------------------------------------------
extern "C" void kernel_launch(void* const* d_in, const int* in_sizes, int n_in,
                              void* d_out, int out_size)
{
    const float* x      = (const float*)d_in[0];
    const int*   eidx   = (const int*)d_in[1];     // int32 (JAX x64 disabled)
    const float* W_conv = (const float*)d_in[2];
    const float* b_conv = (const float*)d_in[3];
    const float* W1     = (const float*)d_in[4];
    const float* b1     = (const float*)d_in[5];
    const float* W2     = (const float*)d_in[6];
    const float* b2     = (const float*)d_in[7];
    const float* W3     = (const float*)d_in[8];
    const float* b3     = (const float*)d_in[9];
    float*       out    = (float*)d_out;

    const int* e_src = eidx;
    const int* e_dst = eidx + N_EDGES;

    // allow 70KB dynamic smem for GEMM kernels (idempotent; immediate, not captured)
    cudaFuncSetAttribute(k_gemm_conv, cudaFuncAttributeMaxDynamicSharedMemorySize, GEMM_SMEM_BYTES);
    cudaFuncSetAttribute(k_gemm_mlp1, cudaFuncAttributeMaxDynamicSharedMemorySize, GEMM_SMEM_BYTES);
    cudaFuncSetAttribute(k_gemm_mlp2, cudaFuncAttributeMaxDynamicSharedMemorySize, GEMM_SMEM_BYTES);

    k_deg_init<<<(N_NODES + 255) / 256, 256>>>();
    k_deg_count<<<(N_EDGES + 255) / 256, 256>>>(e_dst);
    k_dis<<<(N_NODES + 255) / 256, 256>>>();

    // h = x @ W_conv ; agg = dis^2 * h   (selfloop fused into epilogue)
    {
        dim3 grid(IN_CH / BN, (N_NODES + BM - 1) / BM);
        k_gemm_conv<<<grid, 256, GEMM_SMEM_BYTES>>>(x, W_conv);
    }

    // edge scatter into agg
    k_scatter<<<(N_EDGES + 7) / 8, 256>>>(e_src, e_dst);

    // h = relu(agg + b_conv) + x
    {
        size_t tot4 = (size_t)N_NODES * IN_CH / 4;
        k_postconv<<<(unsigned)((tot4 + 255) / 256), 256>>>(x, b_conv);
    }

    // h1 = relu(h @ W1 + b1)
    {
        dim3 grid(MID_CH / BN, (N_NODES + BM - 1) / BM);
        k_gemm_mlp1<<<grid, 256, GEMM_SMEM_BYTES>>>(W1, b1);
    }

    // out = relu(h1 @ W2 + b2) @ W3 + b3   (final fused into mlp2 epilogue)
    k_out_init<<<(N_NODES + 255) / 256, 256>>>(out, b3);
    {
        dim3 grid(MID_CH / BN, (N_NODES + BM - 1) / BM);
        k_gemm_mlp2<<<grid, 256, GEMM_SMEM_BYTES>>>(W2, b2, W3, out);
    }
}